// round 1
// baseline (speedup 1.0000x reference)
#include <cuda_runtime.h>

#define WSZ 7
#define NPIX 49
#define CH 96
#define HEADS 3
#define HD 32
#define HW 56
#define NWH 8
#define BATCH 128

// Pre-transposed weights: [c][m] layouts for coalesced smem staging
__device__ float g_wq_t[CH * 3 * CH];   // 96 x 288
__device__ float g_wp_t[CH * CH];       // 96 x 96

__global__ void prep_kernel(const float* __restrict__ qkv_w,
                            const float* __restrict__ proj_w) {
    int t = blockIdx.x * blockDim.x + threadIdx.x;
    int stride = gridDim.x * blockDim.x;
    for (int i = t; i < 288 * 96; i += stride) {
        int m = i / 96, c = i % 96;
        g_wq_t[c * 288 + m] = qkv_w[i];
    }
    for (int i = t; i < 96 * 96; i += stride) {
        int m = i / 96, c = i % 96;
        g_wp_t[c * 96 + m] = proj_w[i];
    }
}

// Fast exp on the FMA pipe (avoids MUFU.EX2 throughput wall).
// Input is always <= 0 (post max-subtraction); clamp handles mask -100s.
__device__ __forceinline__ float fexp(float x) {
    x = fmaxf(x, -87.0f);
    float n = rintf(x * 1.4426950408889634f);
    float r = fmaf(n, -0.6931471805599453f, x);
    float p = fmaf(r, 8.3333333e-3f, 4.1666667e-2f);
    p = fmaf(p, r, 0.16666667f);
    p = fmaf(p, r, 0.5f);
    p = fmaf(p, r, 1.0f);
    p = fmaf(p, r, 1.0f);
    int e = (int)n;
    return p * __int_as_float((e + 127) << 23);
}

// Shared memory layout (floats):
//  sm_qkv : [0, 14112)        288 x 49   q/k/v, rows [0,96) reused for AV output
//  sm_A   : [14112, 21316)    7204       xn (96x49), then attn (3x49x49)
//  sm_w   : [21316, 23620)    2304       weight chunk staging
//  sm_rel : [23620, 24128)    508        rel_table copy (169x3)
//  sm_mu  : [24128, 24180)
//  sm_rs  : [24180, 24232)
//  sm_lab : [24232, 24284)    int labels
#define SMEM_FLOATS 24284

extern __shared__ float smem[];

__global__ void __launch_bounds__(256, 2)
swin_kernel(const float* __restrict__ x,
            const float* __restrict__ ln_g, const float* __restrict__ ln_b,
            const float* __restrict__ qkv_b,
            const float* __restrict__ proj_b,
            const float* __restrict__ rel_table,
            float* __restrict__ out) {
    float* sm_qkv = smem;
    float* sm_A   = smem + 14112;
    float* sm_w   = smem + 21316;
    float* sm_rel = smem + 23620;
    float* sm_mu  = smem + 24128;
    float* sm_rs  = smem + 24180;
    int*   sm_lab = (int*)(smem + 24232);

    const int t  = threadIdx.x;
    const int wid = blockIdx.x;
    const int b  = wid >> 6;
    const int wr = (wid >> 3) & 7;
    const int wc = wid & 7;

    // ---- Phase 0: rel table, shift-mask labels, gather x (with roll -3), LN ----
    for (int i = t; i < 507; i += 256) sm_rel[i] = __ldg(rel_table + i);
    if (t < NPIX) {
        int pr = t / 7, pc = t % 7;
        int hs = wr * 7 + pr, wsv = wc * 7 + pc;
        int lh = hs < 49 ? 0 : (hs < 53 ? 1 : 2);
        int lw = wsv < 49 ? 0 : (wsv < 53 ? 1 : 2);
        sm_lab[t] = lh * 3 + lw;
    }
    const float* xb = x + (size_t)b * CH * (HW * HW);
    for (int idx = t; idx < CH * NPIX; idx += 256) {
        int c = idx / NPIX, p = idx % NPIX;
        int pr = p / 7, pc = p % 7;
        int gh = wr * 7 + pr + 3; if (gh >= 56) gh -= 56;
        int gw = wc * 7 + pc + 3; if (gw >= 56) gw -= 56;
        sm_A[c * NPIX + p] = __ldg(xb + c * (HW * HW) + gh * HW + gw);
    }
    __syncthreads();
    if (t < NPIX) {
        float s = 0.f, ss = 0.f;
        #pragma unroll 8
        for (int c = 0; c < CH; ++c) {
            float v = sm_A[c * NPIX + t];
            s += v; ss += v * v;
        }
        float mu = s * (1.0f / 96.0f);
        float var = ss * (1.0f / 96.0f) - mu * mu;
        sm_mu[t] = mu;
        sm_rs[t] = rsqrtf(var + 1e-5f);
    }
    __syncthreads();
    for (int idx = t; idx < CH * NPIX; idx += 256) {
        int c = idx / NPIX, p = idx % NPIX;
        sm_A[idx] = (sm_A[idx] - sm_mu[p]) * sm_rs[p] * __ldg(ln_g + c) + __ldg(ln_b + c);
    }
    __syncthreads();

    // ---- Phase 1: QKV GEMM  (288 x 49, K=96), 8m x 7p tiles, 252 threads ----
    {
        const int mg = t / 7, pg = t % 7;
        const int m0 = mg * 8, p0 = pg * 7;
        float acc[56];
        #pragma unroll
        for (int i = 0; i < 56; ++i) acc[i] = 0.f;
        for (int kc = 0; kc < 12; ++kc) {
            for (int idx = t; idx < 2304; idx += 256)
                sm_w[idx] = g_wq_t[kc * 2304 + idx];
            __syncthreads();
            if (t < 252) {
                #pragma unroll
                for (int cc = 0; cc < 8; ++cc) {
                    const float* xr = &sm_A[(kc * 8 + cc) * NPIX + p0];
                    float xv[7];
                    #pragma unroll
                    for (int k = 0; k < 7; ++k) xv[k] = xr[k];
                    const float4 w0 = *(const float4*)&sm_w[cc * 288 + m0];
                    const float4 w1 = *(const float4*)&sm_w[cc * 288 + m0 + 4];
                    float wv[8] = {w0.x, w0.y, w0.z, w0.w, w1.x, w1.y, w1.z, w1.w};
                    #pragma unroll
                    for (int mi = 0; mi < 8; ++mi)
                        #pragma unroll
                        for (int pi = 0; pi < 7; ++pi)
                            acc[mi * 7 + pi] = fmaf(wv[mi], xv[pi], acc[mi * 7 + pi]);
                }
            }
            __syncthreads();
        }
        if (t < 252) {
            #pragma unroll
            for (int mi = 0; mi < 8; ++mi) {
                float bb = __ldg(qkv_b + m0 + mi);
                #pragma unroll
                for (int pi = 0; pi < 7; ++pi)
                    sm_qkv[(m0 + mi) * NPIX + p0 + pi] = acc[mi * 7 + pi] + bb;
            }
        }
    }
    __syncthreads();

    // ---- Phase 2: attention scores QK^T + rel bias + shift mask (147 threads) ----
    if (t < 147) {
        const int h = t / 49, r = t % 49;
        const int ig = r / 7, jg = r % 7;
        const int i0 = ig * 7, j0 = jg * 7;
        float acc[49];
        #pragma unroll
        for (int i = 0; i < 49; ++i) acc[i] = 0.f;
        const float* qb = sm_qkv + (h * HD) * NPIX;
        const float* kb = sm_qkv + (CH + h * HD) * NPIX;
        for (int d = 0; d < HD; ++d) {
            float qv[7], kv[7];
            #pragma unroll
            for (int k = 0; k < 7; ++k) {
                qv[k] = qb[d * NPIX + i0 + k];
                kv[k] = kb[d * NPIX + j0 + k];
            }
            #pragma unroll
            for (int ii = 0; ii < 7; ++ii)
                #pragma unroll
                for (int jj = 0; jj < 7; ++jj)
                    acc[ii * 7 + jj] = fmaf(qv[ii], kv[jj], acc[ii * 7 + jj]);
        }
        const float scale = 0.17677669529663687f;  // 1/sqrt(32)
        #pragma unroll
        for (int ii = 0; ii < 7; ++ii) {
            int i = i0 + ii;
            int li = sm_lab[i];
            #pragma unroll
            for (int jj = 0; jj < 7; ++jj) {
                int j = j0 + jj;
                int idx = (ig - jg + 6) * 13 + (ii - jj + 6);
                float bias = sm_rel[idx * 3 + h];
                float msk = (li == sm_lab[j]) ? 0.f : -100.f;
                sm_A[(h * 49 + i) * 49 + j] = fmaf(acc[ii * 7 + jj], scale, bias + msk);
            }
        }
    }
    __syncthreads();

    // ---- Phase 3: softmax over j (147 rows, polynomial exp on FMA pipe) ----
    if (t < 147) {
        float* row = sm_A + t * 49;
        float mx = -1e30f;
        #pragma unroll 7
        for (int j = 0; j < 49; ++j) mx = fmaxf(mx, row[j]);
        float s = 0.f;
        #pragma unroll 7
        for (int j = 0; j < 49; ++j) {
            float e = fexp(row[j] - mx);
            row[j] = e; s += e;
        }
        float inv = 1.0f / s;
        #pragma unroll 7
        for (int j = 0; j < 49; ++j) row[j] *= inv;
    }
    __syncthreads();

    // ---- Phase 4: AV (out 96 x 49, K=49), 4m x 7p tiles, 168 threads ----
    if (t < 168) {
        const int mg = t / 7, pg = t % 7;
        const int m0 = mg * 4, p0 = pg * 7;
        const int h = m0 >> 5;
        float acc[28];
        #pragma unroll
        for (int i = 0; i < 28; ++i) acc[i] = 0.f;
        const float* vb = sm_qkv + (2 * CH + m0) * NPIX;
        const float* ab = sm_A + (h * 49 + p0) * 49;
        for (int j = 0; j < 49; ++j) {
            float av[7], vv[4];
            #pragma unroll
            for (int k = 0; k < 7; ++k) av[k] = ab[k * 49 + j];
            #pragma unroll
            for (int k = 0; k < 4; ++k) vv[k] = vb[k * NPIX + j];
            #pragma unroll
            for (int mi = 0; mi < 4; ++mi)
                #pragma unroll
                for (int pi = 0; pi < 7; ++pi)
                    acc[mi * 7 + pi] = fmaf(vv[mi], av[pi], acc[mi * 7 + pi]);
        }
        // Stash AV result into dead q rows [0,96) of sm_qkv, c-major
        #pragma unroll
        for (int mi = 0; mi < 4; ++mi)
            #pragma unroll
            for (int pi = 0; pi < 7; ++pi)
                sm_qkv[(m0 + mi) * NPIX + p0 + pi] = acc[mi * 7 + pi];
    }
    __syncthreads();

    // ---- Phase 5: proj GEMM (96 x 49, K=96) + scatter (roll +3) ----
    {
        const int mg = t / 7, pg = t % 7;
        const int m0 = mg * 4, p0 = pg * 7;
        float acc[28];
        #pragma unroll
        for (int i = 0; i < 28; ++i) acc[i] = 0.f;
        for (int kc = 0; kc < 12; ++kc) {
            for (int idx = t; idx < 768; idx += 256)
                sm_w[idx] = g_wp_t[kc * 768 + idx];
            __syncthreads();
            if (t < 168) {
                #pragma unroll
                for (int cc = 0; cc < 8; ++cc) {
                    const float* xr = &sm_qkv[(kc * 8 + cc) * NPIX + p0];
                    float xv[7];
                    #pragma unroll
                    for (int k = 0; k < 7; ++k) xv[k] = xr[k];
                    const float4 w = *(const float4*)&sm_w[cc * 96 + m0];
                    float wv[4] = {w.x, w.y, w.z, w.w};
                    #pragma unroll
                    for (int mi = 0; mi < 4; ++mi)
                        #pragma unroll
                        for (int pi = 0; pi < 7; ++pi)
                            acc[mi * 7 + pi] = fmaf(wv[mi], xv[pi], acc[mi * 7 + pi]);
                }
            }
            __syncthreads();
        }
        if (t < 168) {
            float* ob = out + (size_t)b * CH * (HW * HW);
            int gh = wr * 7 + pg + 3; if (gh >= 56) gh -= 56;
            #pragma unroll
            for (int mi = 0; mi < 4; ++mi) {
                float bb = __ldg(proj_b + m0 + mi);
                float* orow = ob + (m0 + mi) * (HW * HW) + gh * HW;
                #pragma unroll
                for (int pi = 0; pi < 7; ++pi) {
                    int gw = wc * 7 + pi + 3; if (gw >= 56) gw -= 56;
                    orow[gw] = acc[mi * 7 + pi] + bb;
                }
            }
        }
    }
}

extern "C" void kernel_launch(void* const* d_in, const int* in_sizes, int n_in,
                              void* d_out, int out_size) {
    const float* x      = (const float*)d_in[0];
    const float* ln_g   = (const float*)d_in[1];
    const float* ln_b   = (const float*)d_in[2];
    const float* qkv_w  = (const float*)d_in[3];
    const float* qkv_b  = (const float*)d_in[4];
    const float* proj_w = (const float*)d_in[5];
    const float* proj_b = (const float*)d_in[6];
    const float* rel    = (const float*)d_in[7];
    float* out = (float*)d_out;

    cudaFuncSetAttribute(swin_kernel, cudaFuncAttributeMaxDynamicSharedMemorySize,
                         SMEM_FLOATS * (int)sizeof(float));

    prep_kernel<<<64, 256>>>(qkv_w, proj_w);
    swin_kernel<<<BATCH * NWH * NWH, 256, SMEM_FLOATS * sizeof(float)>>>(
        x, ln_g, ln_b, qkv_b, proj_b, rel, out);
}

// round 2
// speedup vs baseline: 1.0379x; 1.0379x over previous
#include <cuda_runtime.h>

#define WSZ 7
#define NPIX 49
#define CH 96
#define HEADS 3
#define HD 32
#define HW 56
#define NWH 8
#define BATCH 128

// Pre-transposed weights: [c][m] layouts for coalesced smem staging
__device__ float g_wq_t[CH * 3 * CH];   // 96 x 288
__device__ float g_wp_t[CH * CH];       // 96 x 96

__global__ void prep_kernel(const float* __restrict__ qkv_w,
                            const float* __restrict__ proj_w) {
    int t = blockIdx.x * blockDim.x + threadIdx.x;
    int stride = gridDim.x * blockDim.x;
    for (int i = t; i < 288 * 96; i += stride) {
        int m = i / 96, c = i % 96;
        g_wq_t[c * 288 + m] = qkv_w[i];
    }
    for (int i = t; i < 96 * 96; i += stride) {
        int m = i / 96, c = i % 96;
        g_wp_t[c * 96 + m] = proj_w[i];
    }
}

// ---- packed f32x2 helpers (dual-FMA on sm_103a; rounding identical to fmaf) ----
typedef unsigned long long u64;

__device__ __forceinline__ void fma2(u64& d, u64 a, u64 b) {
    asm("fma.rn.f32x2 %0, %1, %2, %0;" : "+l"(d) : "l"(a), "l"(b));
}
__device__ __forceinline__ u64 pack2(float lo, float hi) {
    u64 r;
    asm("mov.b64 %0, {%1, %2};" : "=l"(r) : "f"(lo), "f"(hi));
    return r;
}
__device__ __forceinline__ float2 unpack2(u64 v) {
    float2 r;
    asm("mov.b64 {%0, %1}, %2;" : "=f"(r.x), "=f"(r.y) : "l"(v));
    return r;
}

// Fast exp on the FMA pipe (avoids MUFU.EX2 throughput wall).
__device__ __forceinline__ float fexp(float x) {
    x = fmaxf(x, -87.0f);
    float n = rintf(x * 1.4426950408889634f);
    float r = fmaf(n, -0.6931471805599453f, x);
    float p = fmaf(r, 8.3333333e-3f, 4.1666667e-2f);
    p = fmaf(p, r, 0.16666667f);
    p = fmaf(p, r, 0.5f);
    p = fmaf(p, r, 1.0f);
    p = fmaf(p, r, 1.0f);
    int e = (int)n;
    return p * __int_as_float((e + 127) << 23);
}

// Shared memory layout (floats):
//  sm_qkv : [0, 14112)        288 x 49   q/k/v, rows [0,96) reused for AV output
//  sm_A   : [14112, 21316)    xn (96x49), then attn (3x49x49)
//  sm_w   : [21316, 23620)    weight chunk staging
//  sm_rel : [23620, 24128)    rel_table copy (169x3)
//  sm_mu  : [24128, 24180)
//  sm_rs  : [24180, 24232)
//  sm_lab : [24232, 24284)
#define SMEM_FLOATS 24284

extern __shared__ float smem[];

__global__ void __launch_bounds__(256, 2)
swin_kernel(const float* __restrict__ x,
            const float* __restrict__ ln_g, const float* __restrict__ ln_b,
            const float* __restrict__ qkv_b,
            const float* __restrict__ proj_b,
            const float* __restrict__ rel_table,
            float* __restrict__ out) {
    float* sm_qkv = smem;
    float* sm_A   = smem + 14112;
    float* sm_w   = smem + 21316;
    float* sm_rel = smem + 23620;
    float* sm_mu  = smem + 24128;
    float* sm_rs  = smem + 24180;
    int*   sm_lab = (int*)(smem + 24232);

    const int t  = threadIdx.x;
    const int wid = blockIdx.x;
    const int b  = wid >> 6;
    const int wr = (wid >> 3) & 7;
    const int wc = wid & 7;

    // ---- Phase 0: rel table, shift-mask labels, gather x (roll -3), LN ----
    for (int i = t; i < 507; i += 256) sm_rel[i] = __ldg(rel_table + i);
    if (t < NPIX) {
        int pr = t / 7, pc = t % 7;
        int hs = wr * 7 + pr, wsv = wc * 7 + pc;
        int lh = hs < 49 ? 0 : (hs < 53 ? 1 : 2);
        int lw = wsv < 49 ? 0 : (wsv < 53 ? 1 : 2);
        sm_lab[t] = lh * 3 + lw;
    }
    const float* xb = x + (size_t)b * CH * (HW * HW);
    for (int idx = t; idx < CH * NPIX; idx += 256) {
        int c = idx / NPIX, p = idx % NPIX;
        int pr = p / 7, pc = p % 7;
        int gh = wr * 7 + pr + 3; if (gh >= 56) gh -= 56;
        int gw = wc * 7 + pc + 3; if (gw >= 56) gw -= 56;
        sm_A[c * NPIX + p] = __ldg(xb + c * (HW * HW) + gh * HW + gw);
    }
    __syncthreads();
    if (t < NPIX) {
        float s = 0.f, ss = 0.f;
        #pragma unroll 8
        for (int c = 0; c < CH; ++c) {
            float v = sm_A[c * NPIX + t];
            s += v; ss += v * v;
        }
        float mu = s * (1.0f / 96.0f);
        float var = ss * (1.0f / 96.0f) - mu * mu;
        sm_mu[t] = mu;
        sm_rs[t] = rsqrtf(var + 1e-5f);
    }
    __syncthreads();
    for (int idx = t; idx < CH * NPIX; idx += 256) {
        int c = idx / NPIX, p = idx % NPIX;
        sm_A[idx] = (sm_A[idx] - sm_mu[p]) * sm_rs[p] * __ldg(ln_g + c) + __ldg(ln_b + c);
    }
    __syncthreads();

    // ---- Phase 1: QKV GEMM (288 x 49, K=96), 8m x 7p tiles, packed over m ----
    {
        const int mg = t / 7, pg = t % 7;
        const int m0 = mg * 8, p0 = pg * 7;
        u64 acc[4][7];
        #pragma unroll
        for (int a = 0; a < 4; ++a)
            #pragma unroll
            for (int pi = 0; pi < 7; ++pi) acc[a][pi] = 0ull;
        for (int kc = 0; kc < 12; ++kc) {
            for (int idx = t; idx < 2304; idx += 256)
                sm_w[idx] = g_wq_t[kc * 2304 + idx];
            __syncthreads();
            if (t < 252) {
                #pragma unroll
                for (int cc = 0; cc < 8; ++cc) {
                    const float* xr = &sm_A[(kc * 8 + cc) * NPIX + p0];
                    u64 xx[7];
                    #pragma unroll
                    for (int pi = 0; pi < 7; ++pi) {
                        float xv = xr[pi];
                        xx[pi] = pack2(xv, xv);
                    }
                    const float* wr_ = &sm_w[cc * 288 + m0];   // m0 % 8 == 0 -> 8B aligned
                    u64 wp[4];
                    #pragma unroll
                    for (int a = 0; a < 4; ++a)
                        wp[a] = *(const u64*)(wr_ + 2 * a);
                    #pragma unroll
                    for (int a = 0; a < 4; ++a)
                        #pragma unroll
                        for (int pi = 0; pi < 7; ++pi)
                            fma2(acc[a][pi], wp[a], xx[pi]);
                }
            }
            __syncthreads();
        }
        if (t < 252) {
            #pragma unroll
            for (int a = 0; a < 4; ++a) {
                float b0 = __ldg(qkv_b + m0 + 2 * a);
                float b1 = __ldg(qkv_b + m0 + 2 * a + 1);
                #pragma unroll
                for (int pi = 0; pi < 7; ++pi) {
                    float2 u = unpack2(acc[a][pi]);
                    sm_qkv[(m0 + 2 * a) * NPIX + p0 + pi]     = u.x + b0;
                    sm_qkv[(m0 + 2 * a + 1) * NPIX + p0 + pi] = u.y + b1;
                }
            }
        }
    }
    __syncthreads();

    // ---- Phase 2: QK^T + rel bias + shift mask, packed over i ----
    if (t < 147) {
        const int h = t / 49, r = t % 49;
        const int ig = r / 7, jg = r % 7;
        const int i0 = ig * 7, j0 = jg * 7;
        u64 acc2[3][7];
        float acc6[7];
        #pragma unroll
        for (int a = 0; a < 3; ++a)
            #pragma unroll
            for (int jj = 0; jj < 7; ++jj) acc2[a][jj] = 0ull;
        #pragma unroll
        for (int jj = 0; jj < 7; ++jj) acc6[jj] = 0.f;
        const float* qb = sm_qkv + (h * HD) * NPIX;
        const float* kb = sm_qkv + (CH + h * HD) * NPIX;
        for (int d = 0; d < HD; ++d) {
            float qv[7], kv[7];
            #pragma unroll
            for (int k = 0; k < 7; ++k) {
                qv[k] = qb[d * NPIX + i0 + k];
                kv[k] = kb[d * NPIX + j0 + k];
            }
            u64 qp[3];
            #pragma unroll
            for (int a = 0; a < 3; ++a) qp[a] = pack2(qv[2 * a], qv[2 * a + 1]);
            #pragma unroll
            for (int jj = 0; jj < 7; ++jj) {
                u64 kk = pack2(kv[jj], kv[jj]);
                #pragma unroll
                for (int a = 0; a < 3; ++a) fma2(acc2[a][jj], qp[a], kk);
                acc6[jj] = fmaf(qv[6], kv[jj], acc6[jj]);
            }
        }
        const float scale = 0.17677669529663687f;  // 1/sqrt(32)
        float accs[7][7];
        #pragma unroll
        for (int a = 0; a < 3; ++a)
            #pragma unroll
            for (int jj = 0; jj < 7; ++jj) {
                float2 u = unpack2(acc2[a][jj]);
                accs[2 * a][jj] = u.x;
                accs[2 * a + 1][jj] = u.y;
            }
        #pragma unroll
        for (int jj = 0; jj < 7; ++jj) accs[6][jj] = acc6[jj];
        #pragma unroll
        for (int ii = 0; ii < 7; ++ii) {
            int i = i0 + ii;
            int li = sm_lab[i];
            #pragma unroll
            for (int jj = 0; jj < 7; ++jj) {
                int j = j0 + jj;
                int idx = (ig - jg + 6) * 13 + (ii - jj + 6);
                float bias = sm_rel[idx * 3 + h];
                float msk = (li == sm_lab[j]) ? 0.f : -100.f;
                sm_A[(h * 49 + i) * 49 + j] = fmaf(accs[ii][jj], scale, bias + msk);
            }
        }
    }
    __syncthreads();

    // ---- Phase 3: softmax over j ----
    if (t < 147) {
        float* row = sm_A + t * 49;
        float mx = -1e30f;
        #pragma unroll 7
        for (int j = 0; j < 49; ++j) mx = fmaxf(mx, row[j]);
        float s = 0.f;
        #pragma unroll 7
        for (int j = 0; j < 49; ++j) {
            float e = fexp(row[j] - mx);
            row[j] = e; s += e;
        }
        float inv = 1.0f / s;
        #pragma unroll 7
        for (int j = 0; j < 49; ++j) row[j] *= inv;
    }
    __syncthreads();

    // ---- Phase 4: AV (96 x 49, K=49), 4m x 7p tiles, packed over m ----
    if (t < 168) {
        const int mg = t / 7, pg = t % 7;
        const int m0 = mg * 4, p0 = pg * 7;
        const int h = m0 >> 5;
        u64 acc[2][7];
        #pragma unroll
        for (int a = 0; a < 2; ++a)
            #pragma unroll
            for (int pi = 0; pi < 7; ++pi) acc[a][pi] = 0ull;
        const float* vb = sm_qkv + (2 * CH + m0) * NPIX;
        const float* ab = sm_A + (h * 49 + p0) * 49;
        for (int j = 0; j < 49; ++j) {
            u64 ap[7];
            #pragma unroll
            for (int k = 0; k < 7; ++k) {
                float av = ab[k * 49 + j];
                ap[k] = pack2(av, av);
            }
            u64 vp[2];
            vp[0] = pack2(vb[0 * NPIX + j], vb[1 * NPIX + j]);
            vp[1] = pack2(vb[2 * NPIX + j], vb[3 * NPIX + j]);
            #pragma unroll
            for (int a = 0; a < 2; ++a)
                #pragma unroll
                for (int pi = 0; pi < 7; ++pi)
                    fma2(acc[a][pi], vp[a], ap[pi]);
        }
        // Stash AV result into dead q rows [0,96) of sm_qkv, c-major
        #pragma unroll
        for (int a = 0; a < 2; ++a)
            #pragma unroll
            for (int pi = 0; pi < 7; ++pi) {
                float2 u = unpack2(acc[a][pi]);
                sm_qkv[(m0 + 2 * a) * NPIX + p0 + pi]     = u.x;
                sm_qkv[(m0 + 2 * a + 1) * NPIX + p0 + pi] = u.y;
            }
    }
    __syncthreads();

    // ---- Phase 5: proj GEMM (96 x 49, K=96) + scatter (roll +3), packed over m ----
    {
        const int mg = t / 7, pg = t % 7;
        const int m0 = mg * 4, p0 = pg * 7;
        u64 acc[2][7];
        #pragma unroll
        for (int a = 0; a < 2; ++a)
            #pragma unroll
            for (int pi = 0; pi < 7; ++pi) acc[a][pi] = 0ull;
        for (int kc = 0; kc < 12; ++kc) {
            for (int idx = t; idx < 768; idx += 256)
                sm_w[idx] = g_wp_t[kc * 768 + idx];
            __syncthreads();
            if (t < 168) {
                #pragma unroll
                for (int cc = 0; cc < 8; ++cc) {
                    const float* xr = &sm_qkv[(kc * 8 + cc) * NPIX + p0];
                    u64 xx[7];
                    #pragma unroll
                    for (int pi = 0; pi < 7; ++pi) {
                        float xv = xr[pi];
                        xx[pi] = pack2(xv, xv);
                    }
                    const float* wr_ = &sm_w[cc * 96 + m0];    // m0 % 4 == 0 -> 8B aligned
                    u64 wp[2];
                    wp[0] = *(const u64*)(wr_);
                    wp[1] = *(const u64*)(wr_ + 2);
                    #pragma unroll
                    for (int a = 0; a < 2; ++a)
                        #pragma unroll
                        for (int pi = 0; pi < 7; ++pi)
                            fma2(acc[a][pi], wp[a], xx[pi]);
                }
            }
            __syncthreads();
        }
        if (t < 168) {
            float* ob = out + (size_t)b * CH * (HW * HW);
            int gh = wr * 7 + pg + 3; if (gh >= 56) gh -= 56;
            #pragma unroll
            for (int a = 0; a < 2; ++a) {
                float b0 = __ldg(proj_b + m0 + 2 * a);
                float b1 = __ldg(proj_b + m0 + 2 * a + 1);
                float* orow0 = ob + (m0 + 2 * a) * (HW * HW) + gh * HW;
                float* orow1 = ob + (m0 + 2 * a + 1) * (HW * HW) + gh * HW;
                #pragma unroll
                for (int pi = 0; pi < 7; ++pi) {
                    int gw = wc * 7 + pi + 3; if (gw >= 56) gw -= 56;
                    float2 u = unpack2(acc[a][pi]);
                    orow0[gw] = u.x + b0;
                    orow1[gw] = u.y + b1;
                }
            }
        }
    }
}

extern "C" void kernel_launch(void* const* d_in, const int* in_sizes, int n_in,
                              void* d_out, int out_size) {
    const float* x      = (const float*)d_in[0];
    const float* ln_g   = (const float*)d_in[1];
    const float* ln_b   = (const float*)d_in[2];
    const float* qkv_w  = (const float*)d_in[3];
    const float* qkv_b  = (const float*)d_in[4];
    const float* proj_w = (const float*)d_in[5];
    const float* proj_b = (const float*)d_in[6];
    const float* rel    = (const float*)d_in[7];
    float* out = (float*)d_out;

    cudaFuncSetAttribute(swin_kernel, cudaFuncAttributeMaxDynamicSharedMemorySize,
                         SMEM_FLOATS * (int)sizeof(float));

    prep_kernel<<<64, 256>>>(qkv_w, proj_w);
    swin_kernel<<<BATCH * NWH * NWH, 256, SMEM_FLOATS * sizeof(float)>>>(
        x, ln_g, ln_b, qkv_b, proj_b, rel, out);
}

// round 3
// speedup vs baseline: 1.2235x; 1.1788x over previous
#include <cuda_runtime.h>

#define WSZ 7
#define NPIX 49
#define CH 96
#define HEADS 3
#define HD 32
#define HW 56
#define NWH 8
#define BATCH 128

// Pre-transposed weights: [c][m] layouts so m-adjacent pairs are contiguous
__device__ float g_wq_t[CH * 3 * CH];   // 96 x 288
__device__ float g_wp_t[CH * CH];       // 96 x 96

__global__ void prep_kernel(const float* __restrict__ qkv_w,
                            const float* __restrict__ proj_w) {
    int t = blockIdx.x * blockDim.x + threadIdx.x;
    int stride = gridDim.x * blockDim.x;
    for (int i = t; i < 288 * 96; i += stride) {
        int m = i / 96, c = i % 96;
        g_wq_t[c * 288 + m] = qkv_w[i];
    }
    for (int i = t; i < 96 * 96; i += stride) {
        int m = i / 96, c = i % 96;
        g_wp_t[c * 96 + m] = proj_w[i];
    }
}

// ---- packed f32x2 helpers (dual-FMA on sm_103a; rounding identical to fmaf) ----
typedef unsigned long long u64;

__device__ __forceinline__ void fma2(u64& d, u64 a, u64 b) {
    asm("fma.rn.f32x2 %0, %1, %2, %0;" : "+l"(d) : "l"(a), "l"(b));
}
__device__ __forceinline__ u64 pack2(float lo, float hi) {
    u64 r;
    asm("mov.b64 %0, {%1, %2};" : "=l"(r) : "f"(lo), "f"(hi));
    return r;
}
__device__ __forceinline__ float2 unpack2(u64 v) {
    float2 r;
    asm("mov.b64 {%0, %1}, %2;" : "=f"(r.x), "=f"(r.y) : "l"(v));
    return r;
}

// Fast exp on the FMA pipe (avoids MUFU.EX2 throughput wall).
__device__ __forceinline__ float fexp(float x) {
    x = fmaxf(x, -87.0f);
    float n = rintf(x * 1.4426950408889634f);
    float r = fmaf(n, -0.6931471805599453f, x);
    float p = fmaf(r, 8.3333333e-3f, 4.1666667e-2f);
    p = fmaf(p, r, 0.16666667f);
    p = fmaf(p, r, 0.5f);
    p = fmaf(p, r, 1.0f);
    p = fmaf(p, r, 1.0f);
    int e = (int)n;
    return p * __int_as_float((e + 127) << 23);
}

// Shared memory layout (floats):
//  sm_qkv : [0, 14112)        288 x 49   q/k/v; rows [0,96) reused for AV output
//  sm_A   : [14112, 21316)    xn (96x49), then attn (3x49x49)
//  sm_rel : [21316, 21824)    rel_table copy (169x3)
//  sm_mu  : [21824, 21876)
//  sm_rs  : [21876, 21928)
//  sm_lab : [21928, 21980)
#define SMEM_FLOATS 21980

extern __shared__ float smem[];

__global__ void __launch_bounds__(256, 2)
swin_kernel(const float* __restrict__ x,
            const float* __restrict__ ln_g, const float* __restrict__ ln_b,
            const float* __restrict__ qkv_b,
            const float* __restrict__ proj_b,
            const float* __restrict__ rel_table,
            float* __restrict__ out) {
    float* sm_qkv = smem;
    float* sm_A   = smem + 14112;
    float* sm_rel = smem + 21316;
    float* sm_mu  = smem + 21824;
    float* sm_rs  = smem + 21876;
    int*   sm_lab = (int*)(smem + 21928);

    const int t  = threadIdx.x;
    const int wid = blockIdx.x;
    const int b  = wid >> 6;
    const int wr = (wid >> 3) & 7;
    const int wc = wid & 7;

    // ---- Phase 0: rel table, shift-mask labels, gather x (roll -3), LN ----
    for (int i = t; i < 507; i += 256) sm_rel[i] = __ldg(rel_table + i);
    if (t < NPIX) {
        int pr = t / 7, pc = t % 7;
        int hs = wr * 7 + pr, wsv = wc * 7 + pc;
        int lh = hs < 49 ? 0 : (hs < 53 ? 1 : 2);
        int lw = wsv < 49 ? 0 : (wsv < 53 ? 1 : 2);
        sm_lab[t] = lh * 3 + lw;
    }
    const float* xb = x + (size_t)b * CH * (HW * HW);
    for (int idx = t; idx < CH * NPIX; idx += 256) {
        int c = idx / NPIX, p = idx % NPIX;
        int pr = p / 7, pc = p % 7;
        int gh = wr * 7 + pr + 3; if (gh >= 56) gh -= 56;
        int gw = wc * 7 + pc + 3; if (gw >= 56) gw -= 56;
        sm_A[c * NPIX + p] = __ldg(xb + c * (HW * HW) + gh * HW + gw);
    }
    __syncthreads();
    if (t < NPIX) {
        float s = 0.f, ss = 0.f;
        #pragma unroll 8
        for (int c = 0; c < CH; ++c) {
            float v = sm_A[c * NPIX + t];
            s += v; ss += v * v;
        }
        float mu = s * (1.0f / 96.0f);
        float var = ss * (1.0f / 96.0f) - mu * mu;
        sm_mu[t] = mu;
        sm_rs[t] = rsqrtf(var + 1e-5f);
    }
    __syncthreads();
    for (int idx = t; idx < CH * NPIX; idx += 256) {
        int c = idx / NPIX, p = idx % NPIX;
        sm_A[idx] = (sm_A[idx] - sm_mu[p]) * sm_rs[p] * __ldg(ln_g + c) + __ldg(ln_b + c);
    }
    __syncthreads();

    // ---- Phase 1: QKV GEMM (288 x 49, K=96), 8m x 7p tiles ----
    // Weights streamed from global via __ldg (L1/L2-cached) -> ZERO barriers.
    if (t < 252) {
        const int mg = t / 7, pg = t % 7;
        const int m0 = mg * 8, p0 = pg * 7;
        u64 acc[4][7];
        #pragma unroll
        for (int a = 0; a < 4; ++a)
            #pragma unroll
            for (int pi = 0; pi < 7; ++pi) acc[a][pi] = 0ull;
        const float* wb = g_wq_t + m0;         // 32B-aligned (m0 % 8 == 0)
        const float* xr0 = sm_A + p0;
        #pragma unroll 2
        for (int c = 0; c < CH; ++c) {
            ulonglong2 wa = __ldg((const ulonglong2*)(wb + c * 288));
            ulonglong2 wbv = __ldg((const ulonglong2*)(wb + c * 288) + 1);
            u64 wp[4] = {wa.x, wa.y, wbv.x, wbv.y};
            const float* xr = xr0 + c * NPIX;
            u64 xx[7];
            #pragma unroll
            for (int pi = 0; pi < 7; ++pi) {
                float xv = xr[pi];
                xx[pi] = pack2(xv, xv);
            }
            #pragma unroll
            for (int a = 0; a < 4; ++a)
                #pragma unroll
                for (int pi = 0; pi < 7; ++pi)
                    fma2(acc[a][pi], wp[a], xx[pi]);
        }
        #pragma unroll
        for (int a = 0; a < 4; ++a) {
            float b0 = __ldg(qkv_b + m0 + 2 * a);
            float b1 = __ldg(qkv_b + m0 + 2 * a + 1);
            #pragma unroll
            for (int pi = 0; pi < 7; ++pi) {
                float2 u = unpack2(acc[a][pi]);
                sm_qkv[(m0 + 2 * a) * NPIX + p0 + pi]     = u.x + b0;
                sm_qkv[(m0 + 2 * a + 1) * NPIX + p0 + pi] = u.y + b1;
            }
        }
    }
    __syncthreads();

    // ---- Phase 2: QK^T + rel bias + shift mask, packed over i ----
    if (t < 147) {
        const int h = t / 49, r = t % 49;
        const int ig = r / 7, jg = r % 7;
        const int i0 = ig * 7, j0 = jg * 7;
        u64 acc2[3][7];
        float acc6[7];
        #pragma unroll
        for (int a = 0; a < 3; ++a)
            #pragma unroll
            for (int jj = 0; jj < 7; ++jj) acc2[a][jj] = 0ull;
        #pragma unroll
        for (int jj = 0; jj < 7; ++jj) acc6[jj] = 0.f;
        const float* qb = sm_qkv + (h * HD) * NPIX;
        const float* kb = sm_qkv + (CH + h * HD) * NPIX;
        for (int d = 0; d < HD; ++d) {
            float qv[7], kv[7];
            #pragma unroll
            for (int k = 0; k < 7; ++k) {
                qv[k] = qb[d * NPIX + i0 + k];
                kv[k] = kb[d * NPIX + j0 + k];
            }
            u64 qp[3];
            #pragma unroll
            for (int a = 0; a < 3; ++a) qp[a] = pack2(qv[2 * a], qv[2 * a + 1]);
            #pragma unroll
            for (int jj = 0; jj < 7; ++jj) {
                u64 kk = pack2(kv[jj], kv[jj]);
                #pragma unroll
                for (int a = 0; a < 3; ++a) fma2(acc2[a][jj], qp[a], kk);
                acc6[jj] = fmaf(qv[6], kv[jj], acc6[jj]);
            }
        }
        const float scale = 0.17677669529663687f;  // 1/sqrt(32)
        float accs[7][7];
        #pragma unroll
        for (int a = 0; a < 3; ++a)
            #pragma unroll
            for (int jj = 0; jj < 7; ++jj) {
                float2 u = unpack2(acc2[a][jj]);
                accs[2 * a][jj] = u.x;
                accs[2 * a + 1][jj] = u.y;
            }
        #pragma unroll
        for (int jj = 0; jj < 7; ++jj) accs[6][jj] = acc6[jj];
        #pragma unroll
        for (int ii = 0; ii < 7; ++ii) {
            int i = i0 + ii;
            int li = sm_lab[i];
            #pragma unroll
            for (int jj = 0; jj < 7; ++jj) {
                int j = j0 + jj;
                int idx = (ig - jg + 6) * 13 + (ii - jj + 6);
                float bias = sm_rel[idx * 3 + h];
                float msk = (li == sm_lab[j]) ? 0.f : -100.f;
                sm_A[(h * 49 + i) * 49 + j] = fmaf(accs[ii][jj], scale, bias + msk);
            }
        }
    }
    __syncthreads();

    // ---- Phase 3: softmax over j ----
    if (t < 147) {
        float* row = sm_A + t * 49;
        float mx = -1e30f;
        #pragma unroll 7
        for (int j = 0; j < 49; ++j) mx = fmaxf(mx, row[j]);
        float s = 0.f;
        #pragma unroll 7
        for (int j = 0; j < 49; ++j) {
            float e = fexp(row[j] - mx);
            row[j] = e; s += e;
        }
        float inv = 1.0f / s;
        #pragma unroll 7
        for (int j = 0; j < 49; ++j) row[j] *= inv;
    }
    __syncthreads();

    // ---- Phase 4: AV (96 x 49, K=49), 4m x 7p tiles ----
    if (t < 168) {
        const int mg = t / 7, pg = t % 7;
        const int m0 = mg * 4, p0 = pg * 7;
        const int h = m0 >> 5;
        u64 acc[2][7];
        #pragma unroll
        for (int a = 0; a < 2; ++a)
            #pragma unroll
            for (int pi = 0; pi < 7; ++pi) acc[a][pi] = 0ull;
        const float* vb = sm_qkv + (2 * CH + m0) * NPIX;
        const float* ab = sm_A + (h * 49 + p0) * 49;
        for (int j = 0; j < 49; ++j) {
            u64 ap[7];
            #pragma unroll
            for (int k = 0; k < 7; ++k) {
                float av = ab[k * 49 + j];
                ap[k] = pack2(av, av);
            }
            u64 vp[2];
            vp[0] = pack2(vb[0 * NPIX + j], vb[1 * NPIX + j]);
            vp[1] = pack2(vb[2 * NPIX + j], vb[3 * NPIX + j]);
            #pragma unroll
            for (int a = 0; a < 2; ++a)
                #pragma unroll
                for (int pi = 0; pi < 7; ++pi)
                    fma2(acc[a][pi], vp[a], ap[pi]);
        }
        // Stash AV result into dead q rows [0,96) of sm_qkv, c-major
        #pragma unroll
        for (int a = 0; a < 2; ++a)
            #pragma unroll
            for (int pi = 0; pi < 7; ++pi) {
                float2 u = unpack2(acc[a][pi]);
                sm_qkv[(m0 + 2 * a) * NPIX + p0 + pi]     = u.x;
                sm_qkv[(m0 + 2 * a + 1) * NPIX + p0 + pi] = u.y;
            }
    }
    __syncthreads();

    // ---- Phase 5: proj GEMM (96 x 49, K=96) + scatter (roll +3) ----
    // Weights via __ldg -> no staging, no barriers.
    if (t < 168) {
        const int mg = t / 7, pg = t % 7;
        const int m0 = mg * 4, p0 = pg * 7;
        u64 acc[2][7];
        #pragma unroll
        for (int a = 0; a < 2; ++a)
            #pragma unroll
            for (int pi = 0; pi < 7; ++pi) acc[a][pi] = 0ull;
        const float* wb = g_wp_t + m0;          // 16B-aligned (m0 % 4 == 0)
        const float* xr0 = sm_qkv + p0;
        #pragma unroll 4
        for (int c = 0; c < CH; ++c) {
            ulonglong2 wa = __ldg((const ulonglong2*)(wb + c * 96));
            u64 wp[2] = {wa.x, wa.y};
            const float* xr = xr0 + c * NPIX;
            u64 xx[7];
            #pragma unroll
            for (int pi = 0; pi < 7; ++pi) {
                float xv = xr[pi];
                xx[pi] = pack2(xv, xv);
            }
            #pragma unroll
            for (int a = 0; a < 2; ++a)
                #pragma unroll
                for (int pi = 0; pi < 7; ++pi)
                    fma2(acc[a][pi], wp[a], xx[pi]);
        }
        float* ob = out + (size_t)b * CH * (HW * HW);
        int gh = wr * 7 + pg + 3; if (gh >= 56) gh -= 56;
        #pragma unroll
        for (int a = 0; a < 2; ++a) {
            float b0 = __ldg(proj_b + m0 + 2 * a);
            float b1 = __ldg(proj_b + m0 + 2 * a + 1);
            float* orow0 = ob + (m0 + 2 * a) * (HW * HW) + gh * HW;
            float* orow1 = ob + (m0 + 2 * a + 1) * (HW * HW) + gh * HW;
            #pragma unroll
            for (int pi = 0; pi < 7; ++pi) {
                int gw = wc * 7 + pi + 3; if (gw >= 56) gw -= 56;
                float2 u = unpack2(acc[a][pi]);
                orow0[gw] = u.x + b0;
                orow1[gw] = u.y + b1;
            }
        }
    }
}

extern "C" void kernel_launch(void* const* d_in, const int* in_sizes, int n_in,
                              void* d_out, int out_size) {
    const float* x      = (const float*)d_in[0];
    const float* ln_g   = (const float*)d_in[1];
    const float* ln_b   = (const float*)d_in[2];
    const float* qkv_w  = (const float*)d_in[3];
    const float* qkv_b  = (const float*)d_in[4];
    const float* proj_w = (const float*)d_in[5];
    const float* proj_b = (const float*)d_in[6];
    const float* rel    = (const float*)d_in[7];
    float* out = (float*)d_out;

    cudaFuncSetAttribute(swin_kernel, cudaFuncAttributeMaxDynamicSharedMemorySize,
                         SMEM_FLOATS * (int)sizeof(float));

    prep_kernel<<<64, 256>>>(qkv_w, proj_w);
    swin_kernel<<<BATCH * NWH * NWH, 256, SMEM_FLOATS * sizeof(float)>>>(
        x, ln_g, ln_b, qkv_b, proj_b, rel, out);
}

// round 5
// speedup vs baseline: 1.3552x; 1.1076x over previous
#include <cuda_runtime.h>

#define WSZ 7
#define NPIX 49
#define CH 96
#define HEADS 3
#define HD 32
#define HW 56
#define NWH 8
#define BATCH 128

// Pre-transposed weights: [c][m] layouts so m-adjacent pairs are contiguous
__device__ float g_wq_t[CH * 3 * CH];   // 96 x 288
__device__ float g_wp_t[CH * CH];       // 96 x 96

__global__ void prep_kernel(const float* __restrict__ qkv_w,
                            const float* __restrict__ proj_w) {
    int t = blockIdx.x * blockDim.x + threadIdx.x;
    int stride = gridDim.x * blockDim.x;
    for (int i = t; i < 288 * 96; i += stride) {
        int m = i / 96, c = i % 96;
        g_wq_t[c * 288 + m] = qkv_w[i];
    }
    for (int i = t; i < 96 * 96; i += stride) {
        int m = i / 96, c = i % 96;
        g_wp_t[c * 96 + m] = proj_w[i];
    }
}

// ---- packed f32x2 helpers (dual-FMA on sm_103a; rounding identical to fmaf) ----
typedef unsigned long long u64;

__device__ __forceinline__ void fma2(u64& d, u64 a, u64 b) {
    asm("fma.rn.f32x2 %0, %1, %2, %0;" : "+l"(d) : "l"(a), "l"(b));
}
__device__ __forceinline__ u64 pack2(float lo, float hi) {
    u64 r;
    asm("mov.b64 %0, {%1, %2};" : "=l"(r) : "f"(lo), "f"(hi));
    return r;
}
__device__ __forceinline__ float2 unpack2(u64 v) {
    float2 r;
    asm("mov.b64 {%0, %1}, %2;" : "=f"(r.x), "=f"(r.y) : "l"(v));
    return r;
}

// Fast exp on the FMA pipe (avoids MUFU.EX2 throughput wall).
__device__ __forceinline__ float fexp(float x) {
    x = fmaxf(x, -87.0f);
    float n = rintf(x * 1.4426950408889634f);
    float r = fmaf(n, -0.6931471805599453f, x);
    float p = fmaf(r, 8.3333333e-3f, 4.1666667e-2f);
    p = fmaf(p, r, 0.16666667f);
    p = fmaf(p, r, 0.5f);
    p = fmaf(p, r, 1.0f);
    p = fmaf(p, r, 1.0f);
    int e = (int)n;
    return p * __int_as_float((e + 127) << 23);
}

// Shared memory layout (floats) — liveness-aliased to fit 3 CTAs/SM:
//  sm_k   : [0, 4704)       k rows;    after ph4: AV output (96x49)
//  sm_v   : [4704, 9408)    v rows
//  sm_q   : [9408, 14112)   q rows;    after ph2a: attn (part)
//  sm_x   : [14112, 18816)  xn;        after ph2a: attn (rest)
//  attn   : [9408, 16611)   3*49*49 = 7203 floats
//  sm_mu  : [18816, 18865)
//  sm_rs  : [18865, 18914)
//  sm_lab : [18914, 18963)
#define SMEM_FLOATS 18963

extern __shared__ float smem[];

__global__ void __launch_bounds__(256, 3)
swin_kernel(const float* __restrict__ x,
            const float* __restrict__ ln_g, const float* __restrict__ ln_b,
            const float* __restrict__ qkv_b,
            const float* __restrict__ proj_b,
            const float* __restrict__ rel_table,
            float* __restrict__ out) {
    float* sm_k   = smem;
    float* sm_v   = smem + 4704;
    float* sm_q   = smem + 9408;
    float* sm_x   = smem + 14112;
    float* sm_att = smem + 9408;    // aliases q + x after phase-2a
    float* sm_av  = smem;           // aliases k after phase 4
    float* sm_mu  = smem + 18816;
    float* sm_rs  = smem + 18865;
    int*   sm_lab = (int*)(smem + 18914);

    const int t  = threadIdx.x;
    const int wid = blockIdx.x;
    const int b  = wid >> 6;
    const int wr = (wid >> 3) & 7;
    const int wc = wid & 7;

    // ---- Phase 0: shift-mask labels, gather x (roll -3), LN ----
    if (t < NPIX) {
        int pr = t / 7, pc = t % 7;
        int hs = wr * 7 + pr, wsv = wc * 7 + pc;
        int lh = hs < 49 ? 0 : (hs < 53 ? 1 : 2);
        int lw = wsv < 49 ? 0 : (wsv < 53 ? 1 : 2);
        sm_lab[t] = lh * 3 + lw;
    }
    const float* xb = x + (size_t)b * CH * (HW * HW);
    for (int idx = t; idx < CH * NPIX; idx += 256) {
        int c = idx / NPIX, p = idx % NPIX;
        int pr = p / 7, pc = p % 7;
        int gh = wr * 7 + pr + 3; if (gh >= 56) gh -= 56;
        int gw = wc * 7 + pc + 3; if (gw >= 56) gw -= 56;
        sm_x[c * NPIX + p] = __ldg(xb + c * (HW * HW) + gh * HW + gw);
    }
    __syncthreads();
    if (t < NPIX) {
        float s = 0.f, ss = 0.f;
        #pragma unroll 8
        for (int c = 0; c < CH; ++c) {
            float v = sm_x[c * NPIX + t];
            s += v; ss += v * v;
        }
        float mu = s * (1.0f / 96.0f);
        float var = ss * (1.0f / 96.0f) - mu * mu;
        sm_mu[t] = mu;
        sm_rs[t] = rsqrtf(var + 1e-5f);
    }
    __syncthreads();
    for (int idx = t; idx < CH * NPIX; idx += 256) {
        int c = idx / NPIX, p = idx % NPIX;
        sm_x[idx] = (sm_x[idx] - sm_mu[p]) * sm_rs[p] * __ldg(ln_g + c) + __ldg(ln_b + c);
    }
    __syncthreads();

    // ---- Phase 1: QKV GEMM (288 x 49, K=96), 8m x 7p tiles, weights via __ldg ----
    if (t < 252) {
        const int mg = t / 7, pg = t % 7;
        const int m0 = mg * 8, p0 = pg * 7;
        u64 acc[4][7];
        #pragma unroll
        for (int a = 0; a < 4; ++a)
            #pragma unroll
            for (int pi = 0; pi < 7; ++pi) acc[a][pi] = 0ull;
        const float* wb = g_wq_t + m0;         // 32B-aligned (m0 % 8 == 0)
        const float* xr0 = sm_x + p0;
        #pragma unroll 2
        for (int c = 0; c < CH; ++c) {
            ulonglong2 wa = __ldg((const ulonglong2*)(wb + c * 288));
            ulonglong2 wc2 = __ldg((const ulonglong2*)(wb + c * 288) + 1);
            u64 wp[4] = {wa.x, wa.y, wc2.x, wc2.y};
            const float* xr = xr0 + c * NPIX;
            #pragma unroll
            for (int pi = 0; pi < 7; ++pi) {
                float xv = xr[pi];
                u64 xx = pack2(xv, xv);
                #pragma unroll
                for (int a = 0; a < 4; ++a)
                    fma2(acc[a][pi], wp[a], xx);
            }
        }
        float* dst = (m0 < 96) ? (sm_q + m0 * NPIX)
                   : (m0 < 192) ? (sm_k + (m0 - 96) * NPIX)
                   : (sm_v + (m0 - 192) * NPIX);
        #pragma unroll
        for (int a = 0; a < 4; ++a) {
            float b0 = __ldg(qkv_b + m0 + 2 * a);
            float b1 = __ldg(qkv_b + m0 + 2 * a + 1);
            #pragma unroll
            for (int pi = 0; pi < 7; ++pi) {
                float2 u = unpack2(acc[a][pi]);
                dst[(2 * a) * NPIX + p0 + pi]     = u.x + b0;
                dst[(2 * a + 1) * NPIX + p0 + pi] = u.y + b1;
            }
        }
    }
    __syncthreads();

    // ---- Phase 2a: QK^T into registers (packed over i) ----
    u64 acc2[3][7];
    float acc6[7];
    int h = 0, ig = 0, jg = 0;
    if (t < 147) {
        h = t / 49;
        int r = t % 49;
        ig = r / 7; jg = r % 7;
        const int i0 = ig * 7, j0 = jg * 7;
        #pragma unroll
        for (int a = 0; a < 3; ++a)
            #pragma unroll
            for (int jj = 0; jj < 7; ++jj) acc2[a][jj] = 0ull;
        #pragma unroll
        for (int jj = 0; jj < 7; ++jj) acc6[jj] = 0.f;
        const float* qb = sm_q + (h * HD) * NPIX;
        const float* kb = sm_k + (h * HD) * NPIX;
        for (int d = 0; d < HD; ++d) {
            float qv[7], kv[7];
            #pragma unroll
            for (int k = 0; k < 7; ++k) {
                qv[k] = qb[d * NPIX + i0 + k];
                kv[k] = kb[d * NPIX + j0 + k];
            }
            u64 qp[3];
            #pragma unroll
            for (int a = 0; a < 3; ++a) qp[a] = pack2(qv[2 * a], qv[2 * a + 1]);
            #pragma unroll
            for (int jj = 0; jj < 7; ++jj) {
                u64 kk = pack2(kv[jj], kv[jj]);
                #pragma unroll
                for (int a = 0; a < 3; ++a) fma2(acc2[a][jj], qp[a], kk);
                acc6[jj] = fmaf(qv[6], kv[jj], acc6[jj]);
            }
        }
    }
    __syncthreads();   // q, k, xn now dead -> attn may overwrite [9408, 16611)

    // ---- Phase 2b: scale + rel bias + shift mask, store attn ----
    if (t < 147) {
        const int i0 = ig * 7, j0 = jg * 7;
        const float scale = 0.17677669529663687f;  // 1/sqrt(32)
        #pragma unroll
        for (int ii = 0; ii < 7; ++ii) {
            int i = i0 + ii;
            int li = sm_lab[i];
            #pragma unroll
            for (int jj = 0; jj < 7; ++jj) {
                int j = j0 + jj;
                float val;
                if (ii == 6) val = acc6[jj];
                else {
                    float2 u = unpack2(acc2[ii >> 1][jj]);
                    val = (ii & 1) ? u.y : u.x;
                }
                int idx = (ig - jg + 6) * 13 + (ii - jj + 6);
                float bias = __ldg(rel_table + idx * 3 + h);
                float msk = (li == sm_lab[j]) ? 0.f : -100.f;
                sm_att[(h * 49 + i) * 49 + j] = fmaf(val, scale, bias + msk);
            }
        }
    }
    __syncthreads();

    // ---- Phase 3: softmax over j ----
    if (t < 147) {
        float* row = sm_att + t * 49;
        float mx = -1e30f;
        #pragma unroll 7
        for (int j = 0; j < 49; ++j) mx = fmaxf(mx, row[j]);
        float s = 0.f;
        #pragma unroll 7
        for (int j = 0; j < 49; ++j) {
            float e = fexp(row[j] - mx);
            row[j] = e; s += e;
        }
        float inv = 1.0f / s;
        #pragma unroll 7
        for (int j = 0; j < 49; ++j) row[j] *= inv;
    }
    __syncthreads();

    // ---- Phase 4: AV (96 x 49, K=49), 4m x 7p tiles; out -> dead k region ----
    if (t < 168) {
        const int mg = t / 7, pg = t % 7;
        const int m0 = mg * 4, p0 = pg * 7;
        const int hh = m0 >> 5;
        u64 acc[2][7];
        #pragma unroll
        for (int a = 0; a < 2; ++a)
            #pragma unroll
            for (int pi = 0; pi < 7; ++pi) acc[a][pi] = 0ull;
        const float* vb = sm_v + m0 * NPIX;
        const float* ab = sm_att + (hh * 49 + p0) * 49;
        for (int j = 0; j < 49; ++j) {
            u64 vp[2];
            vp[0] = pack2(vb[0 * NPIX + j], vb[1 * NPIX + j]);
            vp[1] = pack2(vb[2 * NPIX + j], vb[3 * NPIX + j]);
            #pragma unroll
            for (int pi = 0; pi < 7; ++pi) {
                float av = ab[pi * 49 + j];
                u64 ap = pack2(av, av);
                #pragma unroll
                for (int a = 0; a < 2; ++a)
                    fma2(acc[a][pi], vp[a], ap);
            }
        }
        #pragma unroll
        for (int a = 0; a < 2; ++a)
            #pragma unroll
            for (int pi = 0; pi < 7; ++pi) {
                float2 u = unpack2(acc[a][pi]);
                sm_av[(m0 + 2 * a) * NPIX + p0 + pi]     = u.x;
                sm_av[(m0 + 2 * a + 1) * NPIX + p0 + pi] = u.y;
            }
    }
    __syncthreads();

    // ---- Phase 5: proj GEMM (96 x 49, K=96) + scatter (roll +3) ----
    if (t < 168) {
        const int mg = t / 7, pg = t % 7;
        const int m0 = mg * 4, p0 = pg * 7;
        u64 acc[2][7];
        #pragma unroll
        for (int a = 0; a < 2; ++a)
            #pragma unroll
            for (int pi = 0; pi < 7; ++pi) acc[a][pi] = 0ull;
        const float* wb = g_wp_t + m0;          // 16B-aligned (m0 % 4 == 0)
        const float* xr0 = sm_av + p0;
        #pragma unroll 4
        for (int c = 0; c < CH; ++c) {
            ulonglong2 wa = __ldg((const ulonglong2*)(wb + c * 96));
            u64 wp[2] = {wa.x, wa.y};
            const float* xr = xr0 + c * NPIX;
            #pragma unroll
            for (int pi = 0; pi < 7; ++pi) {
                float xv = xr[pi];
                u64 xx = pack2(xv, xv);
                #pragma unroll
                for (int a = 0; a < 2; ++a)
                    fma2(acc[a][pi], wp[a], xx);
            }
        }
        float* ob = out + (size_t)b * CH * (HW * HW);
        int gh = wr * 7 + pg + 3; if (gh >= 56) gh -= 56;
        #pragma unroll
        for (int a = 0; a < 2; ++a) {
            float b0 = __ldg(proj_b + m0 + 2 * a);
            float b1 = __ldg(proj_b + m0 + 2 * a + 1);
            float* orow0 = ob + (m0 + 2 * a) * (HW * HW) + gh * HW;
            float* orow1 = ob + (m0 + 2 * a + 1) * (HW * HW) + gh * HW;
            #pragma unroll
            for (int pi = 0; pi < 7; ++pi) {
                int gw = wc * 7 + pi + 3; if (gw >= 56) gw -= 56;
                float2 u = unpack2(acc[a][pi]);
                orow0[gw] = u.x + b0;
                orow1[gw] = u.y + b1;
            }
        }
    }
}

extern "C" void kernel_launch(void* const* d_in, const int* in_sizes, int n_in,
                              void* d_out, int out_size) {
    const float* x      = (const float*)d_in[0];
    const float* ln_g   = (const float*)d_in[1];
    const float* ln_b   = (const float*)d_in[2];
    const float* qkv_w  = (const float*)d_in[3];
    const float* qkv_b  = (const float*)d_in[4];
    const float* proj_w = (const float*)d_in[5];
    const float* proj_b = (const float*)d_in[6];
    const float* rel    = (const float*)d_in[7];
    float* out = (float*)d_out;

    cudaFuncSetAttribute(swin_kernel, cudaFuncAttributeMaxDynamicSharedMemorySize,
                         SMEM_FLOATS * (int)sizeof(float));

    prep_kernel<<<64, 256>>>(qkv_w, proj_w);
    swin_kernel<<<BATCH * NWH * NWH, 256, SMEM_FLOATS * sizeof(float)>>>(
        x, ln_g, ln_b, qkv_b, proj_b, rel, out);
}